// round 7
// baseline (speedup 1.0000x reference)
#include <cuda_runtime.h>
#include <cstdint>

#define BB 16
#define NN 1024
#define DD 128
#define BN (BB*NN)

// ---------------- packed fp32x2 helpers (sm_103a) ----------------
__device__ __forceinline__ void ffma2(uint64_t& d, uint64_t a, uint64_t b) {
    asm("fma.rn.f32x2 %0, %1, %2, %0;" : "+l"(d) : "l"(a), "l"(b));
}
__device__ __forceinline__ float2 unpack2(uint64_t p) {
    float2 v; asm("mov.b64 {%0, %1}, %2;" : "=f"(v.x), "=f"(v.y) : "l"(p)); return v;
}

// ---------------- scratch ----------------
__device__ float g_WwT[DD*DD];
__device__ float g_M  [DD*DD];               // A + A^T
__device__ float g_h  [BN*DD];
__device__ float g_g  [BN*DD];               // g = h @ (A+A^T)
__device__ float g_scores[(size_t)BB*NN*NN]; // exp'd masked numerators
__device__ float g_z  [BB*NN];
__device__ float g_hp [BN*DD];

// ---------------- K0: transpose Ww, form M = A+A^T, zero g_z ----------------
__global__ void k_prep(const float* __restrict__ Ww, const float* __restrict__ A) {
    int i = blockIdx.x * 256 + threadIdx.x;   // 16384 == DD*DD == BB*NN
    int d = i >> 7, f = i & 127;
    g_WwT[f * DD + d] = Ww[d * DD + f];
    g_M[d * DD + f] = A[d * DD + f] + A[f * DD + d];
    g_z[i] = 0.f;
}

// ---------------- K1: fused h = x@Ww^T + Wb ; g = h@M ----------------
__global__ __launch_bounds__(256) void k_h_g(const float* __restrict__ x,
                                             const float* __restrict__ Wb) {
    __shared__ float sX[64 * 128];
    int t = threadIdx.x;
    int tx = t & 31, ty = t >> 5;
    int row0 = blockIdx.x * 64;

    #pragma unroll
    for (int i = 0; i < 32; i++) {
        int idx = i * 256 + t;
        sX[idx] = x[(size_t)row0 * DD + idx];
    }
    __syncthreads();

    float acc[8][4];
    float4 wb4 = *(const float4*)&Wb[tx * 4];
    #pragma unroll
    for (int i = 0; i < 8; i++) { acc[i][0]=wb4.x; acc[i][1]=wb4.y; acc[i][2]=wb4.z; acc[i][3]=wb4.w; }
    for (int f = 0; f < 128; f++) {
        float4 w = *(const float4*)&g_WwT[f * DD + tx * 4];
        #pragma unroll
        for (int i = 0; i < 8; i++) {
            float xv = sX[(ty * 8 + i) * 128 + f];
            acc[i][0] += xv * w.x; acc[i][1] += xv * w.y;
            acc[i][2] += xv * w.z; acc[i][3] += xv * w.w;
        }
    }
    __syncthreads();
    #pragma unroll
    for (int i = 0; i < 8; i++) {
        int r = ty * 8 + i;
        float4 v; v.x = acc[i][0]; v.y = acc[i][1]; v.z = acc[i][2]; v.w = acc[i][3];
        *(float4*)&g_h[(size_t)(row0 + r) * DD + tx * 4] = v;
        *(float4*)&sX[r * 128 + tx * 4] = v;
    }
    __syncthreads();

    float acc2[8][4];
    #pragma unroll
    for (int i = 0; i < 8; i++) { acc2[i][0]=0.f; acc2[i][1]=0.f; acc2[i][2]=0.f; acc2[i][3]=0.f; }
    for (int f = 0; f < 128; f++) {
        float4 m4 = *(const float4*)&g_M[f * DD + tx * 4];
        #pragma unroll
        for (int i = 0; i < 8; i++) {
            float hv = sX[(ty * 8 + i) * 128 + f];
            acc2[i][0] += hv * m4.x; acc2[i][1] += hv * m4.y;
            acc2[i][2] += hv * m4.z; acc2[i][3] += hv * m4.w;
        }
    }
    #pragma unroll
    for (int i = 0; i < 8; i++) {
        float4 v; v.x = acc2[i][0]; v.y = acc2[i][1]; v.z = acc2[i][2]; v.w = acc2[i][3];
        *(float4*)&g_g[(size_t)(row0 + ty * 8 + i) * DD + tx * 4] = v;
    }
}

// ---------------- K3: e_sym = g @ h^T ; exp+mask+colsum fused ----------------
#define SMEM_K3 (128 * 129 * 4)   // 66048 B (transpose buffer dominates the union)
__global__ __launch_bounds__(256) void k_scores(const float* __restrict__ adj) {
    extern __shared__ float sm[];
    float2* sG2 = (float2*)sm;                 // 128 x 33 float2 (dup pairs)
    float*  sHT = sm + 128 * 33 * 2;           // 32 x 130 floats

    int u = blockIdx.x, b = blockIdx.y;
    int tj = 0, rem = u;
    while (rem >= 8 - tj) { rem -= 8 - tj; tj++; }
    int tk = tj + rem;
    int j0 = tj * 128, k0 = tk * 128;

    int t = threadIdx.x, tx = t & 15, ty = t >> 4;
    const float* Hb = g_h + (size_t)b * NN * DD;
    const float* Gb = g_g + (size_t)b * NN * DD;

    uint64_t accp[8][4];
    #pragma unroll
    for (int i = 0; i < 8; i++)
        #pragma unroll
        for (int j = 0; j < 4; j++) accp[i][j] = 0ull;

    for (int ch = 0; ch < 4; ch++) {
        int c = t & 31, r0 = t >> 5;
        #pragma unroll
        for (int i = 0; i < 16; i++) {
            int r = r0 + 8 * i;
            float gv = Gb[(size_t)(j0 + r) * DD + ch * 32 + c];
            sG2[r * 33 + c] = make_float2(gv, gv);
            sHT[c * 130 + r] = Hb[(size_t)(k0 + r) * DD + ch * 32 + c];
        }
        __syncthreads();
        for (int kk = 0; kk < 32; kk++) {
            uint64_t bp[4];
            #pragma unroll
            for (int jj = 0; jj < 4; jj++)
                bp[jj] = *(const uint64_t*)&sHT[kk * 130 + jj * 32 + tx * 2];
            #pragma unroll
            for (int i = 0; i < 8; i++) {
                uint64_t ap = *(const uint64_t*)&sG2[(ty * 8 + i) * 33 + kk];
                #pragma unroll
                for (int jj = 0; jj < 4; jj++)
                    ffma2(accp[i][jj], ap, bp[jj]);
            }
        }
        __syncthreads();
    }

    float acc[8][8];
    #pragma unroll
    for (int i = 0; i < 8; i++)
        #pragma unroll
        for (int jj = 0; jj < 4; jj++) {
            float2 v = unpack2(accp[i][jj]);
            acc[i][2 * jj] = v.x; acc[i][2 * jj + 1] = v.y;
        }

    const float* adjb = adj + (size_t)b * NN * NN;
    float* scb = g_scores + (size_t)b * NN * NN;

    float colp[8];
    #pragma unroll
    for (int jj = 0; jj < 8; jj++) colp[jj] = 0.f;

    #pragma unroll
    for (int i = 0; i < 8; i++) {
        int j = j0 + ty * 8 + i;
        #pragma unroll
        for (int jj = 0; jj < 4; jj++) {
            int k = k0 + jj * 32 + tx * 2;
            float2 am = *(const float2*)&adjb[(size_t)j * NN + k];
            float2 v;
            v.x = am.x > 0.f ? __expf(acc[i][2 * jj + 0]) : 0.f;
            v.y = am.y > 0.f ? __expf(acc[i][2 * jj + 1]) : 0.f;
            colp[2 * jj + 0] += am.x > 0.f ? v.x : 1.f;
            colp[2 * jj + 1] += am.y > 0.f ? v.y : 1.f;
            *(float2*)&scb[(size_t)j * NN + k] = v;
        }
    }

    float* sC = sm;   // 16 x 128 floats
    __syncthreads();
    #pragma unroll
    for (int jj = 0; jj < 4; jj++) {
        sC[ty * 128 + jj * 32 + tx * 2 + 0] = colp[2 * jj + 0];
        sC[ty * 128 + jj * 32 + tx * 2 + 1] = colp[2 * jj + 1];
    }
    __syncthreads();
    if (t < 128) {
        float z = 0.f;
        #pragma unroll
        for (int q = 0; q < 16; q++) z += sC[q * 128 + t];
        atomicAdd(&g_z[b * NN + k0 + t], z);
    }

    if (tj != tk) {
        __syncthreads();
        float* sT = sm;   // 128 x 129 floats
        #pragma unroll
        for (int i = 0; i < 8; i++)
            #pragma unroll
            for (int jj = 0; jj < 4; jj++) {
                sT[(jj * 32 + tx * 2 + 0) * 129 + (ty * 8 + i)] = acc[i][2 * jj + 0];
                sT[(jj * 32 + tx * 2 + 1) * 129 + (ty * 8 + i)] = acc[i][2 * jj + 1];
            }
        __syncthreads();
        int c = t & 127, r0b = t >> 7;
        float zM = 0.f;
        #pragma unroll 4
        for (int p = 0; p < 64; p++) {
            int r = r0b + 2 * p;
            int k = k0 + r, j = j0 + c;
            float am = adjb[(size_t)k * NN + j];
            float ev = am > 0.f ? __expf(sT[r * 129 + c]) : 0.f;
            zM += am > 0.f ? ev : 1.f;
            scb[(size_t)k * NN + j] = ev;
        }
        atomicAdd(&g_z[b * NN + j0 + c], zM);
    }
}

// ---------------- K5: h_prime = relu( (n / z_col) @ h ) ----------------
// 128x128 tile, 256 threads (16x16), 8x8 micro-tile, conflict-free b, dup-a.
// Dynamic smem: sA2 128x33 float2 (33792 B) + sH 32x130 float (16640 B) = 50432 B.
#define SMEM_K5 (128 * 33 * 8 + 32 * 130 * 4)
__global__ __launch_bounds__(256) void k_hprime() {
    extern __shared__ float smem5[];
    float2* sA2 = (float2*)smem5;              // 128 x 33 dup pairs
    float*  sH  = smem5 + 128 * 33 * 2;        // 32 x 130
    int b = blockIdx.y, i0 = blockIdx.x * 128;
    int t = threadIdx.x, tx = t & 15, ty = t >> 4;   // 16 x 16
    const float* scb = g_scores + (size_t)b * NN * NN;
    const float* Hb  = g_h      + (size_t)b * NN * DD;
    const float* zb  = g_z      + b * NN;

    uint64_t accp[8][4];
    #pragma unroll
    for (int i = 0; i < 8; i++)
        #pragma unroll
        for (int jj = 0; jj < 4; jj++) accp[i][jj] = 0ull;

    for (int ch = 0; ch < 32; ch++) {
        int jbase = ch * 32;
        {   // attention tile 128x32 (dup pairs): a = numerator * 1/z
            int c = t & 31, r0 = t >> 5;   // r0 0..7
            float rz = __fdividef(1.0f, zb[jbase + c]);
            #pragma unroll
            for (int p = 0; p < 16; p++) {
                int r = r0 + 8 * p;
                float v = scb[(size_t)(i0 + r) * NN + jbase + c] * rz;
                sA2[r * 33 + c] = make_float2(v, v);
            }
        }
        {   // h tile 32x128
            int c2 = t & 127, r0b = t >> 7;   // r0b 0..1
            #pragma unroll
            for (int p = 0; p < 16; p++) {
                int r = r0b + 2 * p;
                sH[r * 130 + c2] = Hb[(size_t)(jbase + r) * DD + c2];
            }
        }
        __syncthreads();
        for (int kk = 0; kk < 32; kk++) {
            uint64_t bp[4];
            #pragma unroll
            for (int jj = 0; jj < 4; jj++)
                bp[jj] = *(const uint64_t*)&sH[kk * 130 + jj * 32 + tx * 2];
            #pragma unroll
            for (int i = 0; i < 8; i++) {
                uint64_t ap = *(const uint64_t*)&sA2[(ty * 8 + i) * 33 + kk];
                #pragma unroll
                for (int jj = 0; jj < 4; jj++)
                    ffma2(accp[i][jj], ap, bp[jj]);
            }
        }
        __syncthreads();
    }
    float* hpb = g_hp + (size_t)b * NN * DD;
    #pragma unroll
    for (int i = 0; i < 8; i++) {
        int row = i0 + ty * 8 + i;
        #pragma unroll
        for (int jj = 0; jj < 4; jj++) {
            float2 v = unpack2(accp[i][jj]);
            v.x = fmaxf(v.x, 0.f); v.y = fmaxf(v.y, 0.f);
            *(float2*)&hpb[(size_t)row * DD + jj * 32 + tx * 2] = v;
        }
    }
}

// ---------------- K6: gates + output ----------------
__global__ __launch_bounds__(256) void k_out(const float* __restrict__ x,
        const float* __restrict__ wi_u, const float* __restrict__ wi_x,
        const float* __restrict__ wf_u, const float* __restrict__ wf_x,
        const float* __restrict__ wo_u, const float* __restrict__ wo_x,
        float* __restrict__ out) {
    int node = blockIdx.x * 8 + (threadIdx.x >> 5);
    int lane = threadIdx.x & 31;
    size_t base = (size_t)node * DD;
    float hp4[4], x4[4];
    float si = 0.f, sf = 0.f, so = 0.f;
    #pragma unroll
    for (int i = 0; i < 4; i++) {
        int d = lane + 32 * i;
        hp4[i] = g_hp[base + d];
        x4[i]  = x[base + d];
        si += hp4[i] * wi_u[d] + x4[i] * wi_x[d];
        sf += hp4[i] * wf_u[d] + x4[i] * wf_x[d];
        so += hp4[i] * wo_u[d] + x4[i] * wo_x[d];
    }
    #pragma unroll
    for (int off = 16; off; off >>= 1) {
        si += __shfl_xor_sync(0xffffffffu, si, off);
        sf += __shfl_xor_sync(0xffffffffu, sf, off);
        so += __shfl_xor_sync(0xffffffffu, so, off);
    }
    float ic = 1.f / (1.f + __expf(-si));
    float fc = 1.f / (1.f + __expf(-sf));
    float oc = 1.f / (1.f + __expf(-so));
    #pragma unroll
    for (int i = 0; i < 4; i++) {
        int d = lane + 32 * i;
        out[base + d] = oc * tanhf(ic * hp4[i] + fc * x4[i]);
    }
}

// ---------------- launch ----------------
extern "C" void kernel_launch(void* const* d_in, const int* in_sizes, int n_in,
                              void* d_out, int out_size) {
    const float* x    = (const float*)d_in[0];
    const float* adj  = (const float*)d_in[1];
    const float* Ww   = (const float*)d_in[2];
    const float* Wb   = (const float*)d_in[3];
    const float* A    = (const float*)d_in[4];
    const float* wi_u = (const float*)d_in[5];
    const float* wi_x = (const float*)d_in[6];
    const float* wf_u = (const float*)d_in[7];
    const float* wf_x = (const float*)d_in[8];
    const float* wo_u = (const float*)d_in[9];
    const float* wo_x = (const float*)d_in[10];
    float* out = (float*)d_out;

    cudaFuncSetAttribute(k_scores, cudaFuncAttributeMaxDynamicSharedMemorySize, SMEM_K3);
    cudaFuncSetAttribute(k_hprime, cudaFuncAttributeMaxDynamicSharedMemorySize, SMEM_K5);

    k_prep<<<64, 256>>>(Ww, A);
    k_h_g<<<BN / 64, 256>>>(x, Wb);
    k_scores<<<dim3(36, BB), 256, SMEM_K3>>>(adj);
    k_hprime<<<dim3(NN / 128, BB), 256, SMEM_K5>>>();
    k_out<<<BN / 8, 256>>>(x, wi_u, wi_x, wf_u, wf_x, wo_u, wo_x, out);
}

// round 8
// speedup vs baseline: 1.0769x; 1.0769x over previous
#include <cuda_runtime.h>
#include <cstdint>

#define BB 16
#define NN 1024
#define DD 128
#define BN (BB*NN)

// ---------------- packed fp32x2 helpers (sm_103a) ----------------
__device__ __forceinline__ void ffma2(uint64_t& d, uint64_t a, uint64_t b) {
    asm("fma.rn.f32x2 %0, %1, %2, %0;" : "+l"(d) : "l"(a), "l"(b));
}
__device__ __forceinline__ float2 unpack2(uint64_t p) {
    float2 v; asm("mov.b64 {%0, %1}, %2;" : "=f"(v.x), "=f"(v.y) : "l"(p)); return v;
}

// ---------------- scratch ----------------
__device__ float g_WwT[DD*DD];
__device__ float g_M  [DD*DD];               // A + A^T
__device__ float g_h  [BN*DD];
__device__ float g_g  [BN*DD];               // g = h @ (A+A^T)
__device__ float g_scores[(size_t)BB*NN*NN]; // exp'd masked numerators
__device__ float g_z  [BB*NN];
__device__ float g_hp [BN*DD];

// ---------------- K0: transpose Ww, form M = A+A^T, zero g_z ----------------
__global__ void k_prep(const float* __restrict__ Ww, const float* __restrict__ A) {
    int i = blockIdx.x * 256 + threadIdx.x;   // 16384 == DD*DD == BB*NN
    int d = i >> 7, f = i & 127;
    g_WwT[f * DD + d] = Ww[d * DD + f];
    g_M[d * DD + f] = A[d * DD + f] + A[f * DD + d];
    g_z[i] = 0.f;
}

// ---------------- K1: fused h = x@Ww^T + Wb ; g = h@M ----------------
__global__ __launch_bounds__(256) void k_h_g(const float* __restrict__ x,
                                             const float* __restrict__ Wb) {
    __shared__ float sX[64 * 128];
    int t = threadIdx.x;
    int tx = t & 31, ty = t >> 5;
    int row0 = blockIdx.x * 64;

    #pragma unroll
    for (int i = 0; i < 32; i++) {
        int idx = i * 256 + t;
        sX[idx] = x[(size_t)row0 * DD + idx];
    }
    __syncthreads();

    float acc[8][4];
    float4 wb4 = *(const float4*)&Wb[tx * 4];
    #pragma unroll
    for (int i = 0; i < 8; i++) { acc[i][0]=wb4.x; acc[i][1]=wb4.y; acc[i][2]=wb4.z; acc[i][3]=wb4.w; }
    for (int f = 0; f < 128; f++) {
        float4 w = *(const float4*)&g_WwT[f * DD + tx * 4];
        #pragma unroll
        for (int i = 0; i < 8; i++) {
            float xv = sX[(ty * 8 + i) * 128 + f];
            acc[i][0] += xv * w.x; acc[i][1] += xv * w.y;
            acc[i][2] += xv * w.z; acc[i][3] += xv * w.w;
        }
    }
    __syncthreads();
    #pragma unroll
    for (int i = 0; i < 8; i++) {
        int r = ty * 8 + i;
        float4 v; v.x = acc[i][0]; v.y = acc[i][1]; v.z = acc[i][2]; v.w = acc[i][3];
        *(float4*)&g_h[(size_t)(row0 + r) * DD + tx * 4] = v;
        *(float4*)&sX[r * 128 + tx * 4] = v;
    }
    __syncthreads();

    float acc2[8][4];
    #pragma unroll
    for (int i = 0; i < 8; i++) { acc2[i][0]=0.f; acc2[i][1]=0.f; acc2[i][2]=0.f; acc2[i][3]=0.f; }
    for (int f = 0; f < 128; f++) {
        float4 m4 = *(const float4*)&g_M[f * DD + tx * 4];
        #pragma unroll
        for (int i = 0; i < 8; i++) {
            float hv = sX[(ty * 8 + i) * 128 + f];
            acc2[i][0] += hv * m4.x; acc2[i][1] += hv * m4.y;
            acc2[i][2] += hv * m4.z; acc2[i][3] += hv * m4.w;
        }
    }
    #pragma unroll
    for (int i = 0; i < 8; i++) {
        float4 v; v.x = acc2[i][0]; v.y = acc2[i][1]; v.z = acc2[i][2]; v.w = acc2[i][3];
        *(float4*)&g_g[(size_t)(row0 + ty * 8 + i) * DD + tx * 4] = v;
    }
}

// ---------------- K3: e_sym = g @ h^T ; exp+mask+colsum fused (R5 config) ----------------
#define SMEM_K3 (128 * 129 * 4)   // 66048 B (transpose buffer dominates the union)
__global__ __launch_bounds__(256) void k_scores(const float* __restrict__ adj) {
    extern __shared__ float sm[];
    float2* sG2 = (float2*)sm;                 // 128 x 33 float2 (dup pairs)
    float*  sHT = sm + 128 * 33 * 2;           // 32 x 130 floats

    int u = blockIdx.x, b = blockIdx.y;
    int tj = 0, rem = u;
    while (rem >= 8 - tj) { rem -= 8 - tj; tj++; }
    int tk = tj + rem;
    int j0 = tj * 128, k0 = tk * 128;

    int t = threadIdx.x, tx = t & 15, ty = t >> 4;
    const float* Hb = g_h + (size_t)b * NN * DD;
    const float* Gb = g_g + (size_t)b * NN * DD;

    uint64_t accp[8][4];
    #pragma unroll
    for (int i = 0; i < 8; i++)
        #pragma unroll
        for (int j = 0; j < 4; j++) accp[i][j] = 0ull;

    for (int ch = 0; ch < 4; ch++) {
        int c = t & 31, r0 = t >> 5;
        #pragma unroll
        for (int i = 0; i < 16; i++) {
            int r = r0 + 8 * i;
            float gv = Gb[(size_t)(j0 + r) * DD + ch * 32 + c];
            sG2[r * 33 + c] = make_float2(gv, gv);
            sHT[c * 130 + r] = Hb[(size_t)(k0 + r) * DD + ch * 32 + c];
        }
        __syncthreads();
        for (int kk = 0; kk < 32; kk++) {
            uint64_t bp[4];
            #pragma unroll
            for (int jj = 0; jj < 4; jj++)
                bp[jj] = *(const uint64_t*)&sHT[kk * 130 + jj * 32 + tx * 2];
            #pragma unroll
            for (int i = 0; i < 8; i++) {
                uint64_t ap = *(const uint64_t*)&sG2[(ty * 8 + i) * 33 + kk];
                #pragma unroll
                for (int jj = 0; jj < 4; jj++)
                    ffma2(accp[i][jj], ap, bp[jj]);
            }
        }
        __syncthreads();
    }

    float acc[8][8];
    #pragma unroll
    for (int i = 0; i < 8; i++)
        #pragma unroll
        for (int jj = 0; jj < 4; jj++) {
            float2 v = unpack2(accp[i][jj]);
            acc[i][2 * jj] = v.x; acc[i][2 * jj + 1] = v.y;
        }

    const float* adjb = adj + (size_t)b * NN * NN;
    float* scb = g_scores + (size_t)b * NN * NN;

    float colp[8];
    #pragma unroll
    for (int jj = 0; jj < 8; jj++) colp[jj] = 0.f;

    #pragma unroll
    for (int i = 0; i < 8; i++) {
        int j = j0 + ty * 8 + i;
        #pragma unroll
        for (int jj = 0; jj < 4; jj++) {
            int k = k0 + jj * 32 + tx * 2;
            float2 am = *(const float2*)&adjb[(size_t)j * NN + k];
            float2 v;
            v.x = am.x > 0.f ? __expf(acc[i][2 * jj + 0]) : 0.f;
            v.y = am.y > 0.f ? __expf(acc[i][2 * jj + 1]) : 0.f;
            colp[2 * jj + 0] += am.x > 0.f ? v.x : 1.f;
            colp[2 * jj + 1] += am.y > 0.f ? v.y : 1.f;
            *(float2*)&scb[(size_t)j * NN + k] = v;
        }
    }

    float* sC = sm;   // 16 x 128 floats
    __syncthreads();
    #pragma unroll
    for (int jj = 0; jj < 4; jj++) {
        sC[ty * 128 + jj * 32 + tx * 2 + 0] = colp[2 * jj + 0];
        sC[ty * 128 + jj * 32 + tx * 2 + 1] = colp[2 * jj + 1];
    }
    __syncthreads();
    if (t < 128) {
        float z = 0.f;
        #pragma unroll
        for (int q = 0; q < 16; q++) z += sC[q * 128 + t];
        atomicAdd(&g_z[b * NN + k0 + t], z);
    }

    if (tj != tk) {
        __syncthreads();
        float* sT = sm;   // 128 x 129 floats
        #pragma unroll
        for (int i = 0; i < 8; i++)
            #pragma unroll
            for (int jj = 0; jj < 4; jj++) {
                sT[(jj * 32 + tx * 2 + 0) * 129 + (ty * 8 + i)] = acc[i][2 * jj + 0];
                sT[(jj * 32 + tx * 2 + 1) * 129 + (ty * 8 + i)] = acc[i][2 * jj + 1];
            }
        __syncthreads();
        int c = t & 127, r0b = t >> 7;
        float zM = 0.f;
        #pragma unroll 4
        for (int p = 0; p < 64; p++) {
            int r = r0b + 2 * p;
            int k = k0 + r, j = j0 + c;
            float am = adjb[(size_t)k * NN + j];
            float ev = am > 0.f ? __expf(sT[r * 129 + c]) : 0.f;
            zM += am > 0.f ? ev : 1.f;
            scb[(size_t)k * NN + j] = ev;
        }
        atomicAdd(&g_z[b * NN + j0 + c], zM);
    }
}

// ---------------- K5: h_prime = relu( (n / z_col) @ h ) ----------------
// 64x128 tile, 256 threads (32 tx x 8 ty), 8x4 micro-tile.
// b-cols per thread: {tx*2, tx*2+1, 64+tx*2, 64+tx*2+1} -> LDS.64 contiguous (2 phases, min).
// a-operand: dup float2 pairs, broadcast LDS.64. grid 256 -> full chip; ~3 CTAs/SM.
#define SMEM_K5 (64 * 33 * 8 + 32 * 130 * 4)   // 16896 + 16640 = 33536 B
__global__ __launch_bounds__(256) void k_hprime() {
    extern __shared__ float smem5[];
    float2* sA2 = (float2*)smem5;              // 64 x 33 dup pairs
    float*  sH  = smem5 + 64 * 33 * 2;         // 32 x 130
    int b = blockIdx.y, i0 = blockIdx.x * 64;
    int t = threadIdx.x, tx = t & 31, ty = t >> 5;   // 32 x 8
    const float* scb = g_scores + (size_t)b * NN * NN;
    const float* Hb  = g_h      + (size_t)b * NN * DD;
    const float* zb  = g_z      + b * NN;

    uint64_t accp[8][2];
    #pragma unroll
    for (int i = 0; i < 8; i++) { accp[i][0] = 0ull; accp[i][1] = 0ull; }

    for (int ch = 0; ch < 32; ch++) {
        int jbase = ch * 32;
        {   // attention tile 64x32 (dup pairs): a = numerator * 1/z
            int c = tx, r0 = ty;               // c 0..31, r0 0..7
            float rz = __fdividef(1.0f, zb[jbase + c]);
            #pragma unroll
            for (int p = 0; p < 8; p++) {
                int r = r0 + 8 * p;
                float v = scb[(size_t)(i0 + r) * NN + jbase + c] * rz;
                sA2[r * 33 + c] = make_float2(v, v);
            }
        }
        {   // h tile 32x128
            int c2 = t & 127, r0b = t >> 7;    // r0b 0..1
            #pragma unroll
            for (int p = 0; p < 16; p++) {
                int r = r0b + 2 * p;
                sH[r * 130 + c2] = Hb[(size_t)(jbase + r) * DD + c2];
            }
        }
        __syncthreads();
        for (int kk = 0; kk < 32; kk++) {
            uint64_t b0 = *(const uint64_t*)&sH[kk * 130 + tx * 2];
            uint64_t b1 = *(const uint64_t*)&sH[kk * 130 + 64 + tx * 2];
            #pragma unroll
            for (int i = 0; i < 8; i++) {
                uint64_t ap = *(const uint64_t*)&sA2[(ty * 8 + i) * 33 + kk];
                ffma2(accp[i][0], ap, b0);
                ffma2(accp[i][1], ap, b1);
            }
        }
        __syncthreads();
    }
    float* hpb = g_hp + (size_t)b * NN * DD;
    #pragma unroll
    for (int i = 0; i < 8; i++) {
        int row = i0 + ty * 8 + i;
        float2 v0 = unpack2(accp[i][0]);
        float2 v1 = unpack2(accp[i][1]);
        v0.x = fmaxf(v0.x, 0.f); v0.y = fmaxf(v0.y, 0.f);
        v1.x = fmaxf(v1.x, 0.f); v1.y = fmaxf(v1.y, 0.f);
        *(float2*)&hpb[(size_t)row * DD + tx * 2]      = v0;
        *(float2*)&hpb[(size_t)row * DD + 64 + tx * 2] = v1;
    }
}

// ---------------- K6: gates + output ----------------
__global__ __launch_bounds__(256) void k_out(const float* __restrict__ x,
        const float* __restrict__ wi_u, const float* __restrict__ wi_x,
        const float* __restrict__ wf_u, const float* __restrict__ wf_x,
        const float* __restrict__ wo_u, const float* __restrict__ wo_x,
        float* __restrict__ out) {
    int node = blockIdx.x * 8 + (threadIdx.x >> 5);
    int lane = threadIdx.x & 31;
    size_t base = (size_t)node * DD;
    float hp4[4], x4[4];
    float si = 0.f, sf = 0.f, so = 0.f;
    #pragma unroll
    for (int i = 0; i < 4; i++) {
        int d = lane + 32 * i;
        hp4[i] = g_hp[base + d];
        x4[i]  = x[base + d];
        si += hp4[i] * wi_u[d] + x4[i] * wi_x[d];
        sf += hp4[i] * wf_u[d] + x4[i] * wf_x[d];
        so += hp4[i] * wo_u[d] + x4[i] * wo_x[d];
    }
    #pragma unroll
    for (int off = 16; off; off >>= 1) {
        si += __shfl_xor_sync(0xffffffffu, si, off);
        sf += __shfl_xor_sync(0xffffffffu, sf, off);
        so += __shfl_xor_sync(0xffffffffu, so, off);
    }
    float ic = 1.f / (1.f + __expf(-si));
    float fc = 1.f / (1.f + __expf(-sf));
    float oc = 1.f / (1.f + __expf(-so));
    #pragma unroll
    for (int i = 0; i < 4; i++) {
        int d = lane + 32 * i;
        out[base + d] = oc * tanhf(ic * hp4[i] + fc * x4[i]);
    }
}

// ---------------- launch ----------------
extern "C" void kernel_launch(void* const* d_in, const int* in_sizes, int n_in,
                              void* d_out, int out_size) {
    const float* x    = (const float*)d_in[0];
    const float* adj  = (const float*)d_in[1];
    const float* Ww   = (const float*)d_in[2];
    const float* Wb   = (const float*)d_in[3];
    const float* A    = (const float*)d_in[4];
    const float* wi_u = (const float*)d_in[5];
    const float* wi_x = (const float*)d_in[6];
    const float* wf_u = (const float*)d_in[7];
    const float* wf_x = (const float*)d_in[8];
    const float* wo_u = (const float*)d_in[9];
    const float* wo_x = (const float*)d_in[10];
    float* out = (float*)d_out;

    cudaFuncSetAttribute(k_scores, cudaFuncAttributeMaxDynamicSharedMemorySize, SMEM_K3);
    cudaFuncSetAttribute(k_hprime, cudaFuncAttributeMaxDynamicSharedMemorySize, SMEM_K5);

    k_prep<<<64, 256>>>(Ww, A);
    k_h_g<<<BN / 64, 256>>>(x, Wb);
    k_scores<<<dim3(36, BB), 256, SMEM_K3>>>(adj);
    k_hprime<<<dim3(NN / 64, BB), 256, SMEM_K5>>>();
    k_out<<<BN / 8, 256>>>(x, wi_u, wi_x, wf_u, wf_x, wo_u, wo_x, out);
}